// round 10
// baseline (speedup 1.0000x reference)
#include <cuda_runtime.h>
#include <cuda_bf16.h>
#include <float.h>

// Scratch (allocation-free rule: __device__ globals; g_key zero at load and
// re-zeroed by the epilogue CTA for graph-replay determinism).
__device__ unsigned long long g_key[4096];   // per-row packed (ordered_val, ~idx)
__device__ int g_argmax[4096];
__device__ unsigned int g_done = 0;

#define NS        5            // pipeline stages
#define TILE_F4   704          // float4 per tile -> 11264 bytes
#define TILE_B    (TILE_F4 * 16)
#define THREADS   256
#define NCONS     224          // consumer threads (warps 0-6); warp 7 = producer
#define OCC       4            // CTAs per SM -> 4 independent TMA pipelines/SM

__device__ __forceinline__ unsigned int float_ou(float x) {
    unsigned int u = __float_as_uint(x);
    return (u & 0x80000000u) ? ~u : (u | 0x80000000u);
}
__device__ __forceinline__ float ou_float(unsigned int ou) {
    unsigned int u = (ou & 0x80000000u) ? (ou ^ 0x80000000u) : ~ou;
    return __uint_as_float(u);
}
__device__ __forceinline__ unsigned int smem_u32(const void* p) {
    return (unsigned int)__cvta_generic_to_shared(p);
}
__device__ __forceinline__ void mbar_init(unsigned int mbar, unsigned int count) {
    asm volatile("mbarrier.init.shared.b64 [%0], %1;" :: "r"(mbar), "r"(count) : "memory");
}
__device__ __forceinline__ void mbar_expect_tx(unsigned int mbar, unsigned int bytes) {
    asm volatile("mbarrier.arrive.expect_tx.shared.b64 _, [%0], %1;"
                 :: "r"(mbar), "r"(bytes) : "memory");
}
__device__ __forceinline__ void mbar_arrive(unsigned int mbar) {
    asm volatile("mbarrier.arrive.shared.b64 _, [%0];" :: "r"(mbar) : "memory");
}
__device__ __forceinline__ void mbar_wait(unsigned int mbar, unsigned int parity) {
    asm volatile(
        "{\n\t.reg .pred P;\n\t"
        "WAIT_%=:\n\t"
        "mbarrier.try_wait.parity.acquire.cta.shared::cta.b64 P, [%0], %1, 0x989680;\n\t"
        "@P bra.uni DONE_%=;\n\t"
        "bra.uni WAIT_%=;\n\t"
        "DONE_%=:\n\t}"
        :: "r"(mbar), "r"(parity) : "memory");
}
__device__ __forceinline__ void mbar_wait_relaxed(unsigned int mbar, unsigned int parity) {
    asm volatile(
        "{\n\t.reg .pred P;\n\t"
        "WAIT_%=:\n\t"
        "mbarrier.try_wait.parity.relaxed.cta.shared::cta.b64 P, [%0], %1, 0x989680;\n\t"
        "@P bra.uni DONE_%=;\n\t"
        "bra.uni WAIT_%=;\n\t"
        "DONE_%=:\n\t}"
        :: "r"(mbar), "r"(parity) : "memory");
}
__device__ __forceinline__ void bulk_copy_g2s(unsigned int dst_smem, const void* src,
                                              unsigned int bytes, unsigned int mbar) {
    asm volatile(
        "cp.async.bulk.shared::cluster.global.mbarrier::complete_tx::bytes "
        "[%0], [%1], %2, [%3];"
        :: "r"(dst_smem), "l"(src), "r"(bytes), "r"(mbar) : "memory");
}

// ---------------------------------------------------------------------------
// Static continuous pipeline, 4-pipelines-per-SM edition. Each CTA owns a
// static contiguous tile range (tiles never span rows); producer warp 7 lane 0
// drives an NS-deep cp.async.bulk pipeline with no drains; warps 0-6 consume.
// Per-row running argmax merged into g_key[row] via packed atomicMax.
// Last-finishing CTA decodes keys and runs the accept epilogue.
// ---------------------------------------------------------------------------
__global__ __launch_bounds__(THREADS, OCC)
void rejection_sampler_kernel(const float* __restrict__ logits,
                              const unsigned int* __restrict__ spec_words,
                              float* __restrict__ out,
                              int vocab, int rows, int B, int k) {
    extern __shared__ float4 smem[];
    float4* tiles = smem;
    unsigned long long* bar64 =
        reinterpret_cast<unsigned long long*>(smem + NS * TILE_F4);
    const unsigned int bar_base = smem_u32(bar64);
    #define FULL_BAR(s)  (bar_base + 8u * (unsigned)(s))
    #define EMPTY_BAR(s) (bar_base + 8u * (unsigned)(NS + (s)))

    const int tid = threadIdx.x;
    const int wid = tid >> 5;
    const int lid = tid & 31;
    const int nv4 = vocab >> 2;
    const int tpr = nv4 / TILE_F4;             // full tiles per row
    const int rem_f4 = nv4 - tpr * TILE_F4;    // last partial tile (float4)
    const int tpr_all = tpr + (rem_f4 ? 1 : 0);
    const long long total_tiles = (long long)rows * tpr_all;
    const long long per_cta = (total_tiles + gridDim.x - 1) / gridDim.x;
    long long t0 = (long long)blockIdx.x * per_cta;
    long long t1 = t0 + per_cta; if (t1 > total_tiles) t1 = total_tiles;
    const long long ntiles = (t1 > t0) ? (t1 - t0) : 0;

    __shared__ bool s_last;

    if (tid == 0) {
        #pragma unroll
        for (int s = 0; s < NS; s++) {
            mbar_init(FULL_BAR(s), 1);       // completes via expect_tx bytes
            mbar_init(EMPTY_BAR(s), NCONS);  // consumer threads arrive
        }
        asm volatile("fence.proxy.async.shared::cta;" ::: "memory");
    }
    __syncthreads();

    if (ntiles > 0) {
        if (wid == 7) {
            // ----------------- PRODUCER (warp 7, lane 0) -----------------
            if (lid == 0) {
                for (long long g = 0; g < ntiles; g++) {
                    const int s = (int)(g % NS);
                    const long long i = g / NS;
                    if (i >= 1) mbar_wait_relaxed(EMPTY_BAR(s), (unsigned)((i - 1) & 1));
                    const long long gt = t0 + g;
                    const int row  = (int)(gt / tpr_all);
                    const int ti   = (int)(gt % tpr_all);
                    const int n    = (ti < tpr) ? TILE_F4 : rem_f4;
                    const float* src = logits + (size_t)row * vocab
                                              + (size_t)ti * TILE_F4 * 4;
                    mbar_expect_tx(FULL_BAR(s), (unsigned int)(n * 16));
                    bulk_copy_g2s(smem_u32(tiles + (size_t)s * TILE_F4), src,
                                  (unsigned int)(n * 16), FULL_BAR(s));
                }
            }
        } else {
            // ----------------- CONSUMERS (warps 0-6) -----------------
            float best = -FLT_MAX;
            int bidx = 0x7FFFFFFF;
            int cur_row = (int)(t0 / tpr_all);

            for (long long g = 0; g < ntiles; g++) {
                const long long gt = t0 + g;
                const int row = (int)(gt / tpr_all);
                const int ti  = (int)(gt % tpr_all);

                // row-boundary flush (warp-level reduce, then atomic merge)
                if (row != cur_row) {
                    #pragma unroll
                    for (int off = 16; off > 0; off >>= 1) {
                        float ov = __shfl_down_sync(0xFFFFFFFFu, best, off);
                        int   oi = __shfl_down_sync(0xFFFFFFFFu, bidx, off);
                        if (ov > best || (ov == best && oi < bidx)) { best = ov; bidx = oi; }
                    }
                    if (lid == 0 && bidx != 0x7FFFFFFF) {
                        unsigned long long key =
                            ((unsigned long long)float_ou(best) << 32) |
                            (unsigned long long)(unsigned int)(~bidx);
                        atomicMax(&g_key[cur_row], key);
                    }
                    best = -FLT_MAX; bidx = 0x7FFFFFFF;
                    cur_row = row;
                }

                const int s = (int)(g % NS);
                mbar_wait(FULL_BAR(s), (unsigned)((g / NS) & 1));

                const int f4base = ti * TILE_F4;
                const int n = (ti < tpr) ? TILE_F4 : rem_f4;
                const float4* tp = tiles + (size_t)s * TILE_F4;
                for (int j = tid; j < n; j += NCONS) {
                    float4 v = tp[j];
                    int base = (f4base + j) << 2;
                    // Per-thread indices strictly increase within a row, so
                    // strict '>' keeps earliest index (jnp.argmax semantics).
                    if (v.x > best) { best = v.x; bidx = base; }
                    if (v.y > best) { best = v.y; bidx = base + 1; }
                    if (v.z > best) { best = v.z; bidx = base + 2; }
                    if (v.w > best) { best = v.w; bidx = base + 3; }
                }
                mbar_arrive(EMPTY_BAR(s));
            }

            // final flush for the last row in range
            #pragma unroll
            for (int off = 16; off > 0; off >>= 1) {
                float ov = __shfl_down_sync(0xFFFFFFFFu, best, off);
                int   oi = __shfl_down_sync(0xFFFFFFFFu, bidx, off);
                if (ov > best || (ov == best && oi < bidx)) { best = ov; bidx = oi; }
            }
            if (lid == 0 && bidx != 0x7FFFFFFF) {
                unsigned long long key =
                    ((unsigned long long)float_ou(best) << 32) |
                    (unsigned long long)(unsigned int)(~bidx);
                atomicMax(&g_key[cur_row], key);
            }
        }
    }
    __syncthreads();

    // ---- completion counter ----
    if (tid == 0) {
        __threadfence();
        unsigned int prev = atomicAdd(&g_done, 1u);
        s_last = (prev == gridDim.x - 1u);
    }
    __syncthreads();
    if (!s_last) return;
    __threadfence();   // acquire all CTAs' key updates

    // ---- decode per-row argmax (+ scalar tail if vocab % 4 != 0) ----
    const int remv = vocab & 3;
    for (int r = tid; r < rows; r += THREADS) {
        unsigned long long key = g_key[r];
        int idx = ~(int)(unsigned int)(key & 0xFFFFFFFFull);
        if (remv) {
            float val = ou_float((unsigned int)(key >> 32));
            const float* rowp = logits + (size_t)r * vocab;
            for (int c = nv4 << 2; c < vocab; c++) {
                float v = rowp[c];
                if (v > val) { val = v; idx = c; }
            }
        }
        g_argmax[r] = idx;
    }
    __syncthreads();

    // ---- speculative-accept logic ----
    if (tid < B) {
        const int b = tid;
        // spec dtype detection: tokens < 2^17 -> int words < 0x20000;
        // float32 (>=1.0) patterns >= 0x3F800000; int64 -> odd words zero.
        int big = 0, odd_nonzero = 0;
        #pragma unroll
        for (int w = 0; w < 32; w++) {
            unsigned int x = spec_words[w];
            if (x >= 0x01000000u) big++;
            if ((w & 1) && x != 0u) odd_nonzero++;
        }
        int mode = (big > 0) ? 2 : (odd_nonzero == 0 ? 1 : 0); // 2=f32,1=i64,0=i32

        const int kp1 = k + 1;
        int n_acc = 0;
        bool acc = true;
        for (int j = 0; j < k; j++) {
            long long sv;
            if (mode == 2) {
                float f = reinterpret_cast<const float*>(spec_words)[(size_t)b * k + j];
                sv = (long long)f;
            } else if (mode == 1) {
                sv = reinterpret_cast<const long long*>(spec_words)[(size_t)b * k + j];
            } else {
                sv = (long long)reinterpret_cast<const int*>(spec_words)[(size_t)b * k + j];
            }
            int o = g_argmax[b * kp1 + j];
            if (acc && (long long)o == sv) n_acc++; else acc = false;
        }
        for (int j = 0; j < kp1; j++) {
            out[b * kp1 + j] = (j <= n_acc) ? (float)g_argmax[b * kp1 + j] : -1.0f;
        }
    }
    __syncthreads();
    for (int r = tid; r < rows; r += THREADS) g_key[r] = 0ull;
    if (tid == 0) g_done = 0;
}

extern "C" void kernel_launch(void* const* d_in, const int* in_sizes, int n_in,
                              void* d_out, int out_size) {
    const float* logits = (const float*)d_in[0];
    const unsigned int* spec = (const unsigned int*)d_in[1];

    const int rows  = out_size;          // B*(k+1)
    const int nspec = in_sizes[1];       // B*k
    const int B     = rows - nspec;
    const int k     = nspec / B;
    const int vocab = (int)((long long)in_sizes[0] / rows);

    int sms = 148;
    cudaDeviceGetAttribute(&sms, cudaDevAttrMultiProcessorCount, 0);
    const int grid = sms * OCC;          // 4 independent pipelines per SM

    const int smem_bytes = NS * TILE_B + 2 * NS * 8 + 16;   // ~56.5 KB
    static int configured = 0;
    if (!configured) {
        cudaFuncSetAttribute(rejection_sampler_kernel,
                             cudaFuncAttributeMaxDynamicSharedMemorySize, smem_bytes);
        configured = 1;
    }

    rejection_sampler_kernel<<<grid, THREADS, smem_bytes>>>(
        logits, spec, (float*)d_out, vocab, rows, B, k);
}

// round 11
// speedup vs baseline: 1.0888x; 1.0888x over previous
#include <cuda_runtime.h>
#include <cuda_bf16.h>
#include <float.h>

// Scratch (allocation-free rule: __device__ globals; g_key zero at load and
// re-zeroed by the epilogue CTA for graph-replay determinism).
__device__ unsigned long long g_key[4096];   // per-row packed (ordered_val, ~idx)
__device__ int g_argmax[4096];
__device__ unsigned int g_done = 0;

#define NS       6            // pipeline stages (deepened vs R6)
#define TILE_F4  1152         // float4 per tile -> 18432 bytes
#define TILE_B   (TILE_F4 * 16)
#define THREADS  256

__device__ __forceinline__ unsigned int float_ou(float x) {
    unsigned int u = __float_as_uint(x);
    return (u & 0x80000000u) ? ~u : (u | 0x80000000u);
}
__device__ __forceinline__ float ou_float(unsigned int ou) {
    unsigned int u = (ou & 0x80000000u) ? (ou ^ 0x80000000u) : ~ou;
    return __uint_as_float(u);
}
__device__ __forceinline__ unsigned int smem_u32(const void* p) {
    return (unsigned int)__cvta_generic_to_shared(p);
}
__device__ __forceinline__ void mbar_init(unsigned int mbar, unsigned int count) {
    asm volatile("mbarrier.init.shared.b64 [%0], %1;" :: "r"(mbar), "r"(count) : "memory");
}
__device__ __forceinline__ void mbar_expect_tx(unsigned int mbar, unsigned int bytes) {
    asm volatile("mbarrier.arrive.expect_tx.shared.b64 _, [%0], %1;"
                 :: "r"(mbar), "r"(bytes) : "memory");
}
__device__ __forceinline__ void mbar_arrive(unsigned int mbar) {
    asm volatile("mbarrier.arrive.shared.b64 _, [%0];" :: "r"(mbar) : "memory");
}
__device__ __forceinline__ void mbar_wait(unsigned int mbar, unsigned int parity) {
    asm volatile(
        "{\n\t.reg .pred P;\n\t"
        "WAIT_%=:\n\t"
        "mbarrier.try_wait.parity.acquire.cta.shared::cta.b64 P, [%0], %1, 0x989680;\n\t"
        "@P bra.uni DONE_%=;\n\t"
        "bra.uni WAIT_%=;\n\t"
        "DONE_%=:\n\t}"
        :: "r"(mbar), "r"(parity) : "memory");
}
__device__ __forceinline__ void mbar_wait_relaxed(unsigned int mbar, unsigned int parity) {
    asm volatile(
        "{\n\t.reg .pred P;\n\t"
        "WAIT_%=:\n\t"
        "mbarrier.try_wait.parity.relaxed.cta.shared::cta.b64 P, [%0], %1, 0x989680;\n\t"
        "@P bra.uni DONE_%=;\n\t"
        "bra.uni WAIT_%=;\n\t"
        "DONE_%=:\n\t}"
        :: "r"(mbar), "r"(parity) : "memory");
}
__device__ __forceinline__ void bulk_copy_g2s(unsigned int dst_smem, const void* src,
                                              unsigned int bytes, unsigned int mbar) {
    asm volatile(
        "cp.async.bulk.shared::cluster.global.mbarrier::complete_tx::bytes "
        "[%0], [%1], %2, [%3];"
        :: "r"(dst_smem), "l"(src), "r"(bytes), "r"(mbar) : "memory");
}

// ---------------------------------------------------------------------------
// R6 architecture (best measured), deepened pipeline. Global tile index space:
// rows x tiles_per_row (tiles never span rows). Each CTA owns a static
// contiguous tile range and streams it through ONE uninterrupted NS-deep
// cp.async.bulk pipeline (producer inline at tid 0, up to NS-1 tiles ahead).
// Row boundaries only flush the running argmax into g_key[row] (packed
// atomicMax). Last-finishing CTA decodes keys + runs accept logic.
// ---------------------------------------------------------------------------
__global__ __launch_bounds__(THREADS, 2)
void rejection_sampler_kernel(const float* __restrict__ logits,
                              const unsigned int* __restrict__ spec_words,
                              float* __restrict__ out,
                              int vocab, int rows, int B, int k) {
    extern __shared__ float4 smem[];
    float4* tiles = smem;
    unsigned long long* bar64 =
        reinterpret_cast<unsigned long long*>(smem + NS * TILE_F4);
    const unsigned int bar_base = smem_u32(bar64);
    #define FULL_BAR(s)  (bar_base + 8u * (unsigned)(s))
    #define EMPTY_BAR(s) (bar_base + 8u * (unsigned)(NS + (s)))

    const int tid = threadIdx.x;
    const int wid = tid >> 5;
    const int lid = tid & 31;
    const int nv4 = vocab >> 2;
    const int tpr = nv4 / TILE_F4;             // full tiles per row
    const int rem_f4 = nv4 - tpr * TILE_F4;    // last partial tile (float4)
    const int tpr_all = tpr + (rem_f4 ? 1 : 0);
    const long long total_tiles = (long long)rows * tpr_all;
    const long long per_cta = (total_tiles + gridDim.x - 1) / gridDim.x;
    long long t0 = (long long)blockIdx.x * per_cta;
    long long t1 = t0 + per_cta; if (t1 > total_tiles) t1 = total_tiles;
    const long long ntiles = (t1 > t0) ? (t1 - t0) : 0;

    __shared__ float svals[8];
    __shared__ int   sidx[8];
    __shared__ bool  s_last;

    if (tid == 0) {
        #pragma unroll
        for (int s = 0; s < NS; s++) {
            mbar_init(FULL_BAR(s), 1);
            mbar_init(EMPTY_BAR(s), THREADS);
        }
        asm volatile("fence.proxy.async.shared::cta;" ::: "memory");
    }
    __syncthreads();

    if (ntiles > 0) {
        const int P = (int)((ntiles < (long long)(NS - 1)) ? ntiles : (NS - 1));

        auto tile_src_bytes = [&](long long gt, const float** src, unsigned int* bytes) {
            int row  = (int)(gt / tpr_all);
            int ti   = (int)(gt % tpr_all);
            int n = (ti < tpr) ? TILE_F4 : rem_f4;
            *src = logits + (size_t)row * vocab + (size_t)ti * TILE_F4 * 4;
            *bytes = (unsigned int)(n * 16);
        };

        // ---- prologue: fill pipeline ----
        if (tid == 0) {
            for (int p = 0; p < P; p++) {
                const float* src; unsigned int bytes;
                tile_src_bytes(t0 + p, &src, &bytes);
                mbar_expect_tx(FULL_BAR(p), bytes);
                bulk_copy_g2s(smem_u32(tiles + (size_t)p * TILE_F4), src, bytes, FULL_BAR(p));
            }
        }

        float best = -FLT_MAX;
        int bidx = 0x7FFFFFFF;
        int cur_row = (int)(t0 / tpr_all);

        for (long long g = 0; g < ntiles; g++) {
            const long long gt = t0 + g;
            const int row = (int)(gt / tpr_all);
            const int ti  = (int)(gt % tpr_all);

            // ---- row-boundary flush ----
            if (row != cur_row) {
                #pragma unroll
                for (int off = 16; off > 0; off >>= 1) {
                    float ov = __shfl_down_sync(0xFFFFFFFFu, best, off);
                    int   oi = __shfl_down_sync(0xFFFFFFFFu, bidx, off);
                    if (ov > best || (ov == best && oi < bidx)) { best = ov; bidx = oi; }
                }
                if (lid == 0) { svals[wid] = best; sidx[wid] = bidx; }
                __syncthreads();
                if (wid == 0) {
                    float bv = (lid < 8) ? svals[lid] : -FLT_MAX;
                    int   bi = (lid < 8) ? sidx[lid]  : 0x7FFFFFFF;
                    #pragma unroll
                    for (int off = 4; off > 0; off >>= 1) {
                        float ov = __shfl_down_sync(0xFFFFFFFFu, bv, off);
                        int   oi = __shfl_down_sync(0xFFFFFFFFu, bi, off);
                        if (ov > bv || (ov == bv && oi < bi)) { bv = ov; bi = oi; }
                    }
                    if (lid == 0 && bi != 0x7FFFFFFF) {
                        unsigned long long key =
                            ((unsigned long long)float_ou(bv) << 32) |
                            (unsigned long long)(unsigned int)(~bi);
                        atomicMax(&g_key[cur_row], key);
                    }
                }
                __syncthreads();
                best = -FLT_MAX; bidx = 0x7FFFFFFF;
                cur_row = row;
            }

            // ---- consume tile g ----
            const int s = (int)(g % NS);
            mbar_wait(FULL_BAR(s), (unsigned)((g / NS) & 1));

            const int f4base = ti * TILE_F4;
            const int n = (ti < tpr) ? TILE_F4 : rem_f4;
            const float4* tp = tiles + (size_t)s * TILE_F4;
            for (int j = tid; j < n; j += THREADS) {
                float4 v = tp[j];
                int base = (f4base + j) << 2;
                // Per-thread indices strictly increase within a row, so strict
                // '>' keeps the earliest index on ties (jnp.argmax semantics).
                if (v.x > best) { best = v.x; bidx = base; }
                if (v.y > best) { best = v.y; bidx = base + 1; }
                if (v.z > best) { best = v.z; bidx = base + 2; }
                if (v.w > best) { best = v.w; bidx = base + 3; }
            }
            mbar_arrive(EMPTY_BAR(s));

            // ---- produce tile g+P (continuous; never drains) ----
            if (tid == 0 && g + P < ntiles) {
                const long long gg = g + P;
                const int ss = (int)(gg % NS);
                const long long ii = gg / NS;
                if (ii >= 1) mbar_wait_relaxed(EMPTY_BAR(ss), (unsigned)((ii - 1) & 1));
                const float* src; unsigned int bytes;
                tile_src_bytes(t0 + gg, &src, &bytes);
                mbar_expect_tx(FULL_BAR(ss), bytes);
                bulk_copy_g2s(smem_u32(tiles + (size_t)ss * TILE_F4), src, bytes, FULL_BAR(ss));
            }
        }

        // ---- final flush ----
        #pragma unroll
        for (int off = 16; off > 0; off >>= 1) {
            float ov = __shfl_down_sync(0xFFFFFFFFu, best, off);
            int   oi = __shfl_down_sync(0xFFFFFFFFu, bidx, off);
            if (ov > best || (ov == best && oi < bidx)) { best = ov; bidx = oi; }
        }
        if (lid == 0) { svals[wid] = best; sidx[wid] = bidx; }
        __syncthreads();
        if (wid == 0) {
            float bv = (lid < 8) ? svals[lid] : -FLT_MAX;
            int   bi = (lid < 8) ? sidx[lid]  : 0x7FFFFFFF;
            #pragma unroll
            for (int off = 4; off > 0; off >>= 1) {
                float ov = __shfl_down_sync(0xFFFFFFFFu, bv, off);
                int   oi = __shfl_down_sync(0xFFFFFFFFu, bi, off);
                if (ov > bv || (ov == bv && oi < bi)) { bv = ov; bi = oi; }
            }
            if (lid == 0 && bi != 0x7FFFFFFF) {
                unsigned long long key =
                    ((unsigned long long)float_ou(bv) << 32) |
                    (unsigned long long)(unsigned int)(~bi);
                atomicMax(&g_key[cur_row], key);
            }
        }
    }
    __syncthreads();

    // ---- completion counter ----
    if (tid == 0) {
        __threadfence();
        unsigned int prev = atomicAdd(&g_done, 1u);
        s_last = (prev == gridDim.x - 1u);
    }
    __syncthreads();
    if (!s_last) return;
    __threadfence();   // acquire all CTAs' key updates

    // ---- decode per-row argmax (+ scalar tail if vocab % 4 != 0) ----
    const int remv = vocab & 3;
    for (int r = tid; r < rows; r += THREADS) {
        unsigned long long key = g_key[r];
        int idx = ~(int)(unsigned int)(key & 0xFFFFFFFFull);
        if (remv) {
            float val = ou_float((unsigned int)(key >> 32));
            const float* rowp = logits + (size_t)r * vocab;
            for (int c = nv4 << 2; c < vocab; c++) {
                float v = rowp[c];
                if (v > val) { val = v; idx = c; }
            }
        }
        g_argmax[r] = idx;
    }
    __syncthreads();

    // ---- speculative-accept logic ----
    if (tid < B) {
        const int b = tid;
        // spec dtype detection: tokens < 2^17 -> int words < 0x20000;
        // float32 (>=1.0) patterns >= 0x3F800000; int64 -> odd words zero.
        int big = 0, odd_nonzero = 0;
        #pragma unroll
        for (int w = 0; w < 32; w++) {
            unsigned int x = spec_words[w];
            if (x >= 0x01000000u) big++;
            if ((w & 1) && x != 0u) odd_nonzero++;
        }
        int mode = (big > 0) ? 2 : (odd_nonzero == 0 ? 1 : 0); // 2=f32,1=i64,0=i32

        const int kp1 = k + 1;
        int n_acc = 0;
        bool acc = true;
        for (int j = 0; j < k; j++) {
            long long sv;
            if (mode == 2) {
                float f = reinterpret_cast<const float*>(spec_words)[(size_t)b * k + j];
                sv = (long long)f;
            } else if (mode == 1) {
                sv = reinterpret_cast<const long long*>(spec_words)[(size_t)b * k + j];
            } else {
                sv = (long long)reinterpret_cast<const int*>(spec_words)[(size_t)b * k + j];
            }
            int o = g_argmax[b * kp1 + j];
            if (acc && (long long)o == sv) n_acc++; else acc = false;
        }
        for (int j = 0; j < kp1; j++) {
            out[b * kp1 + j] = (j <= n_acc) ? (float)g_argmax[b * kp1 + j] : -1.0f;
        }
    }
    __syncthreads();
    for (int r = tid; r < rows; r += THREADS) g_key[r] = 0ull;
    if (tid == 0) g_done = 0;
}

extern "C" void kernel_launch(void* const* d_in, const int* in_sizes, int n_in,
                              void* d_out, int out_size) {
    const float* logits = (const float*)d_in[0];
    const unsigned int* spec = (const unsigned int*)d_in[1];

    const int rows  = out_size;          // B*(k+1)
    const int nspec = in_sizes[1];       // B*k
    const int B     = rows - nspec;
    const int k     = nspec / B;
    const int vocab = (int)((long long)in_sizes[0] / rows);

    int sms = 148;
    cudaDeviceGetAttribute(&sms, cudaDevAttrMultiProcessorCount, 0);
    const int grid = sms * 2;            // 2 pipelines/SM, ~110.7KB smem each

    const int smem_bytes = NS * TILE_B + 2 * NS * 8 + 16;
    static int configured = 0;
    if (!configured) {
        cudaFuncSetAttribute(rejection_sampler_kernel,
                             cudaFuncAttributeMaxDynamicSharedMemorySize, smem_bytes);
        configured = 1;
    }

    rejection_sampler_kernel<<<grid, THREADS, smem_bytes>>>(
        logits, spec, (float*)d_out, vocab, rows, B, k);
}